// round 4
// baseline (speedup 1.0000x reference)
#include <cuda_runtime.h>
#include <math.h>

// ---------------- fixed geometry ----------------
#define IMG    512
#define NDET   768
#define NVIEWS 360

#define DG_D    (1.2858 / (595.0 + 490.6))        // DGAMMA (double)
#define DGF     ((float)DG_D)
#define INVDG_D ((595.0 + 490.6) / 1.2858)        // 1/DGAMMA
#define DSOF    595.0f
#define PIXF    0.7433f
#define SCALEF  ((float)(2.0 * M_PI / 360.0))
#define DYF     (8.0f * PIXF)                      // slot stride in y (mm)
#define G0F     ((float)(1.0 / (8.0 * DG_D * DG_D)))

// atan poly coefficients, pre-scaled by 1/DGAMMA (Taylor deg-11; |t|<=0.625)
#define C1  ((float)( INVDG_D))
#define C3  ((float)(-INVDG_D / 3.0))
#define C5  ((float)( INVDG_D / 5.0))
#define C7  ((float)(-INVDG_D / 7.0))
#define C9  ((float)( INVDG_D / 9.0))
#define C11 ((float)(-INVDG_D / 11.0))

// ---------------- device scratch ----------------
__device__ float4 d_qi[NVIEWS * NDET];   // (q0[k], q0[k+1], q1[k], q1[k+1])

// ramp kernel value g[i], i <-> n = i-767; zero-padded for i > 1534
__device__ __forceinline__ float ramp_g(int i) {
    if (i > 2 * NDET - 2) return 0.0f;
    int n = i - (NDET - 1);
    if (n == 0) return G0F;
    if ((n & 1) == 0) return 0.0f;
    float s = (float)M_PI * sinf((float)n * DGF);
    return __fdividef(-0.5f, s * s);
}

// ---------------- 1) ramp filter (direct sparse convolution) ----------------
// q[k] = DG * ( p1[k]*g0 + sum_{j : (k-j) odd} p1[j]*g[k-j] )
// One block per view. Thread t owns k = t, t+256, t+512 (same parity).
__global__ void __launch_bounds__(256) filter_kernel(const float* __restrict__ proj) {
    __shared__ float4 gq[2 * NDET - 1];   // (g[i], g[i+256], g[i+512])
    __shared__ float2 p01[NDET];          // cosine-weighted proj, both batches
    __shared__ float  qs0[NDET], qs1[NDET];

    const int v = blockIdx.x;
    const int t = threadIdx.x;

    for (int i = t; i < 2 * NDET - 1; i += 256)
        gq[i] = make_float4(ramp_g(i), ramp_g(i + 256), ramp_g(i + 512), 0.0f);

    const float* p0 = proj + (size_t)v * NDET;
    const float* p1 = proj + (size_t)(NVIEWS + v) * NDET;
    for (int j = t; j < NDET; j += 256) {
        float cw = DSOF * cosf(((float)j - 383.5f) * DGF);
        p01[j] = make_float2(p0[j] * cw, p1[j] * cw);
    }
    __syncthreads();

    const int k0 = t;
    float2 pc0 = p01[k0], pc1 = p01[k0 + 256], pc2 = p01[k0 + 512];
    float a00 = pc0.x * G0F, a01 = pc1.x * G0F, a02 = pc2.x * G0F;
    float a10 = pc0.y * G0F, a11 = pc1.y * G0F, a12 = pc2.y * G0F;

    const int j0 = (k0 & 1) ^ 1;   // opposite parity -> odd (k-j) only
    #pragma unroll 4
    for (int j = j0; j < NDET; j += 2) {
        float2 p = p01[j];
        float4 g = gq[k0 - j + (NDET - 1)];
        a00 = fmaf(p.x, g.x, a00);
        a01 = fmaf(p.x, g.y, a01);
        a02 = fmaf(p.x, g.z, a02);
        a10 = fmaf(p.y, g.x, a10);
        a11 = fmaf(p.y, g.y, a11);
        a12 = fmaf(p.y, g.z, a12);
    }

    qs0[k0]       = a00 * DGF;  qs1[k0]       = a10 * DGF;
    qs0[k0 + 256] = a01 * DGF;  qs1[k0 + 256] = a11 * DGF;
    qs0[k0 + 512] = a02 * DGF;  qs1[k0 + 512] = a12 * DGF;
    __syncthreads();

    for (int k = t; k < NDET; k += 256) {
        int k1 = min(k + 1, NDET - 1);
        d_qi[v * NDET + k] = make_float4(qs0[k], qs0[k1], qs1[k], qs1[k1]);
    }
}

// ---------------- 2) pixel-driven backprojection ----------------
// Block = 256 threads covering a 32x32 pixel tile.
// Warp tile: 8(x) x 4(y); warps arranged 4x2; each thread owns 4 pixels (y += 8s).
__global__ void __launch_bounds__(256) backproj_kernel(float* __restrict__ out) {
    __shared__ float4 strig[NVIEWS];   // (cb, sb, sb*DY, cb*DY)

    const int t = threadIdx.x;
    for (int v = t; v < NVIEWS; v += 256) {
        float beta = (float)v * SCALEF;
        float sv, cv;
        sincosf(beta, &sv, &cv);
        strig[v] = make_float4(cv, sv, sv * DYF, cv * DYF);
    }
    __syncthreads();

    const int lane = t & 31, w = t >> 5;
    const int lx = lane & 7, ly = lane >> 3;
    const int wx = w & 3,   wy = w >> 2;
    const int x  = blockIdx.x * 32 + wx * 8 + lx;
    const int y0 = blockIdx.y * 32 + wy * 4 + ly;

    const float X  = ((float)x  - 255.5f) * PIXF;
    const float Y0 = ((float)y0 - 255.5f) * PIXF;

    float acc0[4] = {0.f, 0.f, 0.f, 0.f};
    float acc1[4] = {0.f, 0.f, 0.f, 0.f};

    const float4* qp = d_qi;
    #pragma unroll 2
    for (int v = 0; v < NVIEWS; v++, qp += NDET) {
        float4 tr = strig[v];
        float cb = tr.x, sb = tr.y, sbDY = tr.z, cbDY = tr.w;

        float vx     = fmaf(-DSOF, cb, X);
        float vy0    = fmaf(-DSOF, sb, Y0);
        float dot0   = DSOF - fmaf(X, cb, Y0 * sb);    // always > 0 in-image
        float cross0 = fmaf(sb, vx, -(cb * vy0));

        #pragma unroll
        for (int s = 0; s < 4; s++) {
            float dt = fmaf(-(float)s, sbDY, dot0);
            float cr = fmaf(-(float)s, cbDY, cross0);

            float tt = __fdividef(cr, dt);
            float tc = fminf(fmaxf(tt, -0.625f), 0.625f);
            float t2 = tc * tc;
            float p  = fmaf(C11, t2, C9);
            p = fmaf(p, t2, C7);
            p = fmaf(p, t2, C5);
            p = fmaf(p, t2, C3);
            p = fmaf(p, t2, C1);
            float gidx = fmaf(tc, p, 383.5f);          // atan(t)/DG + 383.5

            bool valid = (gidx >= 0.0f) && (gidx <= 767.0f);
            int i0 = (int)gidx;
            i0 = max(0, min(i0, NDET - 2));
            float wgt = gidx - (float)i0;

            float4 qv = __ldg(&qp[i0]);
            float L2  = fmaf(dt, dt, cr * cr);         // == vx^2 + vy^2
            float rin = valid ? __fdividef(1.0f, L2) : 0.0f;

            float v0 = fmaf(wgt, qv.y - qv.x, qv.x);
            float v1 = fmaf(wgt, qv.w - qv.z, qv.z);
            acc0[s] = fmaf(v0, rin, acc0[s]);
            acc1[s] = fmaf(v1, rin, acc1[s]);
        }
    }

    #pragma unroll
    for (int s = 0; s < 4; s++) {
        int y = y0 + s * 8;
        out[(size_t)y * IMG + x]                     = acc0[s] * SCALEF;
        out[(size_t)IMG * IMG + (size_t)y * IMG + x] = acc1[s] * SCALEF;
    }
}

// ---------------- launch ----------------
extern "C" void kernel_launch(void* const* d_in, const int* in_sizes, int n_in,
                              void* d_out, int out_size) {
    (void)in_sizes; (void)n_in; (void)out_size;
    const float* proj = (const float*)d_in[0];
    float* out = (float*)d_out;

    filter_kernel<<<NVIEWS, 256>>>(proj);
    backproj_kernel<<<dim3(IMG / 32, IMG / 32), 256>>>(out);
}

// round 8
// speedup vs baseline: 1.2798x; 1.2798x over previous
#include <cuda_runtime.h>
#include <math.h>

// ---------------- fixed geometry ----------------
#define IMG    512
#define NDET   768
#define NVIEWS 360

#define DG_D    (1.2858 / (595.0 + 490.6))        // DGAMMA (double)
#define DGF     ((float)DG_D)
#define INVDG_D ((595.0 + 490.6) / 1.2858)        // 1/DGAMMA
#define DSOF    595.0f
#define PIXF    0.7433f
#define SCALEF  ((float)(2.0 * M_PI / 360.0))
#define DYF     (8.0f * PIXF)                      // slot stride in y (mm)
#define G0F     ((float)(1.0 / (8.0 * DG_D * DG_D)))

// atan poly coefficients, pre-scaled by 1/DGAMMA (Taylor deg-15; |t| <= 0.506)
#define C1  ((float)( INVDG_D))
#define C3  ((float)(-INVDG_D / 3.0))
#define C5  ((float)( INVDG_D / 5.0))
#define C7  ((float)(-INVDG_D / 7.0))
#define C9  ((float)( INVDG_D / 9.0))
#define C11 ((float)(-INVDG_D / 11.0))
#define C13 ((float)( INVDG_D / 13.0))
#define C15 ((float)(-INVDG_D / 15.0))

// ---------------- device scratch ----------------
__device__ float4 d_qi[NVIEWS * NDET];   // (q0[k], q0[k+1], q1[k], q1[k+1])

// ramp kernel value g[i], i <-> n = i-767; zero-padded for i > 1534
__device__ __forceinline__ float ramp_g(int i) {
    if (i > 2 * NDET - 2) return 0.0f;
    int n = i - (NDET - 1);
    if (n == 0) return G0F;
    if ((n & 1) == 0) return 0.0f;
    float s = (float)M_PI * sinf((float)n * DGF);
    return __fdividef(-0.5f, s * s);
}

// ---------------- 1) ramp filter (direct sparse convolution) ----------------
// q[k] = DG * ( p1[k]*g0 + sum_{j : (k-j) odd} p1[j]*g[k-j] )
// One block per view. Thread t owns k = t, t+256, t+512 (same parity).
__global__ void __launch_bounds__(256) filter_kernel(const float* __restrict__ proj) {
    __shared__ float4 gq[2 * NDET - 1];   // (g[i], g[i+256], g[i+512])
    __shared__ float2 p01[NDET];          // cosine-weighted proj, both batches
    __shared__ float  qs0[NDET], qs1[NDET];

    const int v = blockIdx.x;
    const int t = threadIdx.x;

    for (int i = t; i < 2 * NDET - 1; i += 256)
        gq[i] = make_float4(ramp_g(i), ramp_g(i + 256), ramp_g(i + 512), 0.0f);

    const float* p0 = proj + (size_t)v * NDET;
    const float* p1 = proj + (size_t)(NVIEWS + v) * NDET;
    for (int j = t; j < NDET; j += 256) {
        float cw = DSOF * cosf(((float)j - 383.5f) * DGF);
        p01[j] = make_float2(p0[j] * cw, p1[j] * cw);
    }
    __syncthreads();

    const int k0 = t;
    float2 pc0 = p01[k0], pc1 = p01[k0 + 256], pc2 = p01[k0 + 512];
    float a00 = pc0.x * G0F, a01 = pc1.x * G0F, a02 = pc2.x * G0F;
    float a10 = pc0.y * G0F, a11 = pc1.y * G0F, a12 = pc2.y * G0F;

    const int j0 = (k0 & 1) ^ 1;   // opposite parity -> odd (k-j) only
    #pragma unroll 4
    for (int j = j0; j < NDET; j += 2) {
        float2 p = p01[j];
        float4 g = gq[k0 - j + (NDET - 1)];
        a00 = fmaf(p.x, g.x, a00);
        a01 = fmaf(p.x, g.y, a01);
        a02 = fmaf(p.x, g.z, a02);
        a10 = fmaf(p.y, g.x, a10);
        a11 = fmaf(p.y, g.y, a11);
        a12 = fmaf(p.y, g.z, a12);
    }

    qs0[k0]       = a00 * DGF;  qs1[k0]       = a10 * DGF;
    qs0[k0 + 256] = a01 * DGF;  qs1[k0 + 256] = a11 * DGF;
    qs0[k0 + 512] = a02 * DGF;  qs1[k0 + 512] = a12 * DGF;
    __syncthreads();

    for (int k = t; k < NDET; k += 256) {
        int k1 = min(k + 1, NDET - 1);
        d_qi[v * NDET + k] = make_float4(qs0[k], qs0[k1], qs1[k], qs1[k1]);
    }
}

// ---------------- 2) pixel-driven backprojection ----------------
// Block = 256 threads covering a 32x16 pixel tile (grid 16x32 = 512 CTAs,
// all co-resident). Warp tile 8(x) x 4(y); warps 4x2; 2 slots/thread (y += 8).
__global__ void __launch_bounds__(256) backproj_kernel(float* __restrict__ out) {
    __shared__ float4 strig[NVIEWS];   // (cb, sb, sb*DY, cb*DY)

    const int t = threadIdx.x;
    for (int v = t; v < NVIEWS; v += 256) {
        float beta = (float)v * SCALEF;
        float sv, cv;
        sincosf(beta, &sv, &cv);
        strig[v] = make_float4(cv, sv, sv * DYF, cv * DYF);
    }
    __syncthreads();

    const int lane = t & 31, w = t >> 5;
    const int lx = lane & 7, ly = lane >> 3;
    const int wx = w & 3,   wy = w >> 2;
    const int x  = blockIdx.x * 32 + wx * 8 + lx;
    const int y0 = blockIdx.y * 16 + wy * 4 + ly;

    const float X  = ((float)x  - 255.5f) * PIXF;
    const float Y0 = ((float)y0 - 255.5f) * PIXF;

    float acc0[2] = {0.f, 0.f};
    float acc1[2] = {0.f, 0.f};

    const float4* qp = d_qi;
    #pragma unroll 2
    for (int v = 0; v < NVIEWS; v++, qp += NDET) {
        float4 tr = strig[v];
        float cb = tr.x, sb = tr.y, sbDY = tr.z, cbDY = tr.w;

        float vx     = fmaf(-DSOF, cb, X);
        float vy0    = fmaf(-DSOF, sb, Y0);
        float dot0   = DSOF - fmaf(X, cb, Y0 * sb);    // always > 0 in-image
        float cross0 = fmaf(sb, vx, -(cb * vy0));

        #pragma unroll
        for (int s = 0; s < 2; s++) {
            float dt = (s == 0) ? dot0   : dot0   - sbDY;
            float cr = (s == 0) ? cross0 : cross0 - cbDY;

            // |tt| <= 0.506 geometrically; deg-15 Taylor error < 3e-4 bins
            float tt = __fdividef(cr, dt);
            float t2 = tt * tt;
            float p  = fmaf(C15, t2, C13);
            p = fmaf(p, t2, C11);
            p = fmaf(p, t2, C9);
            p = fmaf(p, t2, C7);
            p = fmaf(p, t2, C5);
            p = fmaf(p, t2, C3);
            p = fmaf(p, t2, C1);
            float gidx = fmaf(tt, p, 383.5f);          // atan(t)/DG + 383.5

            bool valid = fabsf(gidx - 383.5f) <= 383.5f;   // gidx in [0,767]
            float gc = fminf(fmaxf(gidx, 0.0f), 766.999939f);
            int i0 = (int)gc;
            float wgt = gc - (float)i0;

            float4 qv = __ldg(&qp[i0]);
            float L2  = fmaf(dt, dt, cr * cr);         // == vx^2 + vy^2
            float rin = valid ? __fdividef(1.0f, L2) : 0.0f;

            float v0 = fmaf(wgt, qv.y - qv.x, qv.x);
            float v1 = fmaf(wgt, qv.w - qv.z, qv.z);
            acc0[s] = fmaf(v0, rin, acc0[s]);
            acc1[s] = fmaf(v1, rin, acc1[s]);
        }
    }

    #pragma unroll
    for (int s = 0; s < 2; s++) {
        int y = y0 + s * 8;
        out[(size_t)y * IMG + x]                     = acc0[s] * SCALEF;
        out[(size_t)IMG * IMG + (size_t)y * IMG + x] = acc1[s] * SCALEF;
    }
}

// ---------------- launch ----------------
extern "C" void kernel_launch(void* const* d_in, const int* in_sizes, int n_in,
                              void* d_out, int out_size) {
    (void)in_sizes; (void)n_in; (void)out_size;
    const float* proj = (const float*)d_in[0];
    float* out = (float*)d_out;

    filter_kernel<<<NVIEWS, 256>>>(proj);
    backproj_kernel<<<dim3(IMG / 32, IMG / 16), 256>>>(out);
}

// round 12
// speedup vs baseline: 1.5949x; 1.2462x over previous
#include <cuda_runtime.h>
#include <math.h>

// ---------------- fixed geometry ----------------
#define IMG    512
#define NDET   768
#define NVIEWS 360
#define QSTRIDE 772            // float4 row stride (768 + guards + pad)

#define DG_D    (1.2858 / (595.0 + 490.6))        // DGAMMA (double)
#define DGF     ((float)DG_D)
#define INVDG_D ((595.0 + 490.6) / 1.2858)        // 1/DGAMMA
#define DSOF    595.0f
#define PIXF    0.7433f
#define SCALEF  ((float)(2.0 * M_PI / 360.0))
#define G0F     ((float)(1.0 / (8.0 * DG_D * DG_D)))

// atan poly coefficients, pre-scaled by 1/DGAMMA (Taylor deg-19; |t| <= 0.506,
// tail t^21/21 -> ~3e-5 detector bins)
#define C1  ((float)( INVDG_D))
#define C3  ((float)(-INVDG_D / 3.0))
#define C5  ((float)( INVDG_D / 5.0))
#define C7  ((float)(-INVDG_D / 7.0))
#define C9  ((float)( INVDG_D / 9.0))
#define C11 ((float)(-INVDG_D / 11.0))
#define C13 ((float)( INVDG_D / 13.0))
#define C15 ((float)(-INVDG_D / 15.0))
#define C17 ((float)( INVDG_D / 17.0))
#define C19 ((float)(-INVDG_D / 19.0))

// ---------------- device scratch ----------------
// Row v, local index k in [-1, 768]: physical d_qi[v*QSTRIDE + 1 + k].
// k in [0,766]: (q0[k], q0[k+1], q1[k], q1[k+1]); k = -1 and k = 767: zeros.
__device__ float4 d_qi[NVIEWS * QSTRIDE];

// ramp kernel value g[i], i <-> n = i-767; zero for i > 1534
__device__ __forceinline__ float ramp_g(int i) {
    if (i > 2 * NDET - 2) return 0.0f;
    int n = i - (NDET - 1);
    if (n == 0) return G0F;
    if ((n & 1) == 0) return 0.0f;
    float s = (float)M_PI * sinf((float)n * DGF);
    return __fdividef(-0.5f, s * s);
}

// ---------------- 1) ramp filter (direct sparse convolution) ----------------
// q[k] = DG * ( p1[k]*g0 + sum_{j : (k-j) odd} p1[j]*g[k-j] )
// One block (384 threads) per view. Thread t owns k = t and k = t+384 (same parity).
__global__ void __launch_bounds__(384) filter_kernel(const float* __restrict__ proj) {
    __shared__ float2 g2[2 * NDET - 1];   // (g[i], g[i+384])
    __shared__ float2 p01[NDET];          // cosine-weighted proj, both batches
    __shared__ float  qs0[NDET], qs1[NDET];

    const int v = blockIdx.x;
    const int t = threadIdx.x;

    for (int i = t; i < 2 * NDET - 1; i += 384)
        g2[i] = make_float2(ramp_g(i), ramp_g(i + 384));

    const float* p0 = proj + (size_t)v * NDET;
    const float* p1 = proj + (size_t)(NVIEWS + v) * NDET;
    for (int j = t; j < NDET; j += 384) {
        float cw = DSOF * cosf(((float)j - 383.5f) * DGF);
        p01[j] = make_float2(p0[j] * cw, p1[j] * cw);
    }
    __syncthreads();

    const int k0 = t;                      // outputs k0 and k0+384 (same parity)
    float2 pc0 = p01[k0], pc1 = p01[k0 + 384];
    float a00 = pc0.x * G0F, a01 = pc1.x * G0F;   // batch 0
    float a10 = pc0.y * G0F, a11 = pc1.y * G0F;   // batch 1

    const int j0 = (k0 & 1) ^ 1;           // opposite parity -> odd (k-j) only
    #pragma unroll 4
    for (int j = j0; j < NDET; j += 2) {
        float2 p = p01[j];
        float2 g = g2[k0 - j + (NDET - 1)];
        a00 = fmaf(p.x, g.x, a00);
        a01 = fmaf(p.x, g.y, a01);
        a10 = fmaf(p.y, g.x, a10);
        a11 = fmaf(p.y, g.y, a11);
    }

    qs0[k0]       = a00 * DGF;  qs1[k0]       = a10 * DGF;
    qs0[k0 + 384] = a01 * DGF;  qs1[k0 + 384] = a11 * DGF;
    __syncthreads();

    // pack pairs + zero guards (local -1 and 767)
    float4* row = d_qi + (size_t)v * QSTRIDE + 1;
    for (int k = t; k < NDET; k += 384) {
        row[k] = (k < NDET - 1)
               ? make_float4(qs0[k], qs0[k + 1], qs1[k], qs1[k + 1])
               : make_float4(0.f, 0.f, 0.f, 0.f);      // k == 767 guard
    }
    if (t == 0) row[-1] = make_float4(0.f, 0.f, 0.f, 0.f);
}

// ---------------- 2) pixel-driven backprojection ----------------
// Block = 256 threads = one 32x8 pixel tile (grid 16x64 = 1024 CTAs).
// Warp tile 8(x) x 4(y); warps arranged 4(x) x 2(y). One pixel per thread.
__global__ void __launch_bounds__(256, 6) backproj_kernel(float* __restrict__ out) {
    __shared__ float2 strig[NVIEWS];   // (cos b, sin b)

    const int t = threadIdx.x;
    for (int v = t; v < NVIEWS; v += 256) {
        float sv, cv;
        sincosf((float)v * SCALEF, &sv, &cv);
        strig[v] = make_float2(cv, sv);
    }
    __syncthreads();

    const int lane = t & 31, w = t >> 5;
    const int lx = lane & 7, ly = lane >> 3;
    const int wx = w & 3,   wy = w >> 2;
    const int x = blockIdx.x * 32 + wx * 8 + lx;
    const int y = blockIdx.y * 8  + wy * 4 + ly;

    const float X = ((float)x - 255.5f) * PIXF;
    const float Y = ((float)y - 255.5f) * PIXF;

    float acc0 = 0.0f, acc1 = 0.0f;

    const float4* qp = d_qi + 1;
    #pragma unroll 2
    for (int v = 0; v < NVIEWS; v++, qp += QSTRIDE) {
        float2 tr = strig[v];
        float cb = tr.x, sb = tr.y;

        // rotated coords: dot along central ray (>0), cross transverse
        float dt = fmaf(-Y, sb, fmaf(-X, cb, DSOF));
        float cr = fmaf(-Y, cb, X * sb);

        float tt = __fdividef(cr, dt);                 // |tt| <= 0.506 geometrically
        float t2 = tt * tt;
        float p  = fmaf(C19, t2, C17);
        p = fmaf(p, t2, C15);
        p = fmaf(p, t2, C13);
        p = fmaf(p, t2, C11);
        p = fmaf(p, t2, C9);
        p = fmaf(p, t2, C7);
        p = fmaf(p, t2, C5);
        p = fmaf(p, t2, C3);
        p = fmaf(p, t2, C1);
        float gidx = fmaf(tt, p, 383.5f);              // atan(t)/DG + 383.5

        // clamp into guard range: out-of-fan hits zero entries, contributes 0
        float gc = fminf(fmaxf(gidx, -1.0f), 767.0f);
        float fi = floorf(gc);
        float wgt = gc - fi;
        int   i0 = (int)fi;                            // in [-1, 767]

        float4 qv = __ldg(&qp[i0]);
        float L2  = fmaf(dt, dt, cr * cr);             // == vx^2 + vy^2
        float rin = __fdividef(1.0f, L2);

        float v0 = fmaf(wgt, qv.y - qv.x, qv.x);
        float v1 = fmaf(wgt, qv.w - qv.z, qv.z);
        acc0 = fmaf(v0, rin, acc0);
        acc1 = fmaf(v1, rin, acc1);
    }

    out[(size_t)y * IMG + x]                     = acc0 * SCALEF;
    out[(size_t)IMG * IMG + (size_t)y * IMG + x] = acc1 * SCALEF;
}

// ---------------- launch ----------------
extern "C" void kernel_launch(void* const* d_in, const int* in_sizes, int n_in,
                              void* d_out, int out_size) {
    (void)in_sizes; (void)n_in; (void)out_size;
    const float* proj = (const float*)d_in[0];
    float* out = (float*)d_out;

    filter_kernel<<<NVIEWS, 384>>>(proj);
    backproj_kernel<<<dim3(IMG / 32, IMG / 8), 256>>>(out);
}

// round 15
// speedup vs baseline: 1.7514x; 1.0981x over previous
#include <cuda_runtime.h>
#include <math.h>

// ---------------- fixed geometry ----------------
#define IMG    512
#define NDET   768
#define NVIEWS 360
#define NPAIR  (NVIEWS / 2)
#define QSTRIDE 800            // float4 row stride: 16 guard + 768 data + 16 guard
#define QBASE   16             // data starts at physical index 16

#define DG_D    (1.2858 / (595.0 + 490.6))        // DGAMMA (double)
#define DGF     ((float)DG_D)
#define INVDG_D ((595.0 + 490.6) / 1.2858)        // 1/DGAMMA
#define DSOF    595.0f
#define PIXF    0.7433f
#define SCALEF  ((float)(2.0 * M_PI / 360.0))
#define G0F     ((float)(1.0 / (8.0 * DG_D * DG_D)))

// atan poly coefficients, pre-scaled by 1/DGAMMA (Taylor deg-19; |t| <= 0.506)
#define C1  ((float)( INVDG_D))
#define C3  ((float)(-INVDG_D / 3.0))
#define C5  ((float)( INVDG_D / 5.0))
#define C7  ((float)(-INVDG_D / 7.0))
#define C9  ((float)( INVDG_D / 9.0))
#define C11 ((float)(-INVDG_D / 11.0))
#define C13 ((float)( INVDG_D / 13.0))
#define C15 ((float)(-INVDG_D / 15.0))
#define C17 ((float)( INVDG_D / 17.0))
#define C19 ((float)(-INVDG_D / 19.0))

// ---------------- f32x2 packed helpers (sm_100+) ----------------
typedef unsigned long long ull;
__device__ __forceinline__ ull pk2(float lo, float hi) {
    ull r; asm("mov.b64 %0, {%1, %2};" : "=l"(r) : "f"(lo), "f"(hi)); return r;
}
__device__ __forceinline__ void upk2(ull v, float& lo, float& hi) {
    asm("mov.b64 {%0, %1}, %2;" : "=f"(lo), "=f"(hi) : "l"(v));
}
__device__ __forceinline__ ull fma2(ull a, ull b, ull c) {
    ull r; asm("fma.rn.f32x2 %0, %1, %2, %3;" : "=l"(r) : "l"(a), "l"(b), "l"(c)); return r;
}
__device__ __forceinline__ ull mul2(ull a, ull b) {
    ull r; asm("mul.rn.f32x2 %0, %1, %2;" : "=l"(r) : "l"(a), "l"(b)); return r;
}

// ---------------- device scratch ----------------
// Row v occupies d_qi[v*QSTRIDE .. +799]. Local index k in [-16, 783] maps to
// physical QBASE + k. Entry for k in [0,766]: (q0[k], q1[k], q0[k+1], q1[k+1]).
// All other entries (guards, k=767..783, k<0) are zeros.
__device__ float4 d_qi[NVIEWS * QSTRIDE];

// ramp kernel value g[i], i <-> n = i-767; zero for i > 1534
__device__ __forceinline__ float ramp_g(int i) {
    if (i > 2 * NDET - 2) return 0.0f;
    int n = i - (NDET - 1);
    if (n == 0) return G0F;
    if ((n & 1) == 0) return 0.0f;
    float s = (float)M_PI * sinf((float)n * DGF);
    return __fdividef(-0.5f, s * s);
}

// ---------------- 1) ramp filter (direct sparse convolution) ----------------
// One block (192 threads) per view. Thread t owns k = t, t+192, t+384, t+576.
// g4[i] = (g(i), g(i+192), g(i+384), g(i+576)); tap index i = k0 - j + 767 in [0,958].
__global__ void __launch_bounds__(192) filter_kernel(const float* __restrict__ proj) {
    __shared__ float4 g4[959];
    __shared__ float2 p01[NDET];          // cosine-weighted proj, both batches
    __shared__ float  qs0[NDET], qs1[NDET];

    const int v = blockIdx.x;
    const int t = threadIdx.x;

    for (int i = t; i < 959; i += 192)
        g4[i] = make_float4(ramp_g(i), ramp_g(i + 192), ramp_g(i + 384), ramp_g(i + 576));

    const float* p0 = proj + (size_t)v * NDET;
    const float* p1 = proj + (size_t)(NVIEWS + v) * NDET;
    for (int j = t; j < NDET; j += 192) {
        float cw = DSOF * cosf(((float)j - 383.5f) * DGF);
        p01[j] = make_float2(p0[j] * cw, p1[j] * cw);
    }
    __syncthreads();

    const int k0 = t;                     // outputs k0 + 192*m, m = 0..3 (same parity)
    float2 pc0 = p01[k0], pc1 = p01[k0 + 192], pc2 = p01[k0 + 384], pc3 = p01[k0 + 576];
    // packed accumulators: A* -> outputs (k0, k0+192), B* -> (k0+384, k0+576)
    ull A0 = pk2(pc0.x * G0F, pc1.x * G0F);     // batch 0
    ull A1 = pk2(pc0.y * G0F, pc1.y * G0F);     // batch 1
    ull B0 = pk2(pc2.x * G0F, pc3.x * G0F);
    ull B1 = pk2(pc2.y * G0F, pc3.y * G0F);

    const int j0 = (k0 & 1) ^ 1;          // opposite parity -> odd (k-j) only
    #pragma unroll 4
    for (int j = j0; j < NDET; j += 2) {
        float2 p = p01[j];
        float4 g = g4[k0 - j + (NDET - 1)];
        ull px2 = pk2(p.x, p.x);
        ull py2 = pk2(p.y, p.y);
        ull g01 = pk2(g.x, g.y);
        ull g23 = pk2(g.z, g.w);
        A0 = fma2(px2, g01, A0);
        A1 = fma2(py2, g01, A1);
        B0 = fma2(px2, g23, B0);
        B1 = fma2(py2, g23, B1);
    }

    float a0, a1, b0, b1;
    upk2(A0, a0, a1); qs0[k0] = a0 * DGF; qs0[k0 + 192] = a1 * DGF;
    upk2(A1, a0, a1); qs1[k0] = a0 * DGF; qs1[k0 + 192] = a1 * DGF;
    upk2(B0, b0, b1); qs0[k0 + 384] = b0 * DGF; qs0[k0 + 576] = b1 * DGF;
    upk2(B1, b0, b1); qs1[k0 + 384] = b0 * DGF; qs1[k0 + 576] = b1 * DGF;
    __syncthreads();

    // write row: entry k = (q0[k], q1[k], q0[k+1], q1[k+1]) for k in [0,766];
    // everything else (guards) zero.
    float4* row = d_qi + (size_t)v * QSTRIDE;        // physical base
    for (int i = t; i < QSTRIDE; i += 192) {
        int k = i - QBASE;
        row[i] = (k >= 0 && k < NDET - 1)
               ? make_float4(qs0[k], qs1[k], qs0[k + 1], qs1[k + 1])
               : make_float4(0.f, 0.f, 0.f, 0.f);
    }
}

// ---------------- 2) pixel-driven backprojection ----------------
// Block = 256 threads = one 32x8 pixel tile (grid 16x64 = 1024 CTAs).
// Warp tile 8(x) x 4(y). One pixel per thread; views processed in pairs with
// f32x2 packed arithmetic. No bounds checks: guard zeros absorb out-of-fan.
__global__ void __launch_bounds__(256) backproj_kernel(float* __restrict__ out) {
    __shared__ float4 strig[NPAIR];   // (cb_A, cb_B, sb_A, sb_B) per view pair

    const int t = threadIdx.x;
    if (t < NPAIR) {
        float sA, cA, sB, cB;
        sincosf((float)(2 * t)     * SCALEF, &sA, &cA);
        sincosf((float)(2 * t + 1) * SCALEF, &sB, &cB);
        strig[t] = make_float4(cA, cB, sA, sB);
    }
    __syncthreads();

    const int lane = t & 31, w = t >> 5;
    const int lx = lane & 7, ly = lane >> 3;
    const int wx = w & 3,   wy = w >> 2;
    const int x = blockIdx.x * 32 + wx * 8 + lx;
    const int y = blockIdx.y * 8  + wy * 4 + ly;

    const float X = ((float)x - 255.5f) * PIXF;
    const float Y = ((float)y - 255.5f) * PIXF;

    // hoisted packed constants
    const ull X2   = pk2(X, X);
    const ull Y2   = pk2(Y, Y);
    const ull nY2  = pk2(-Y, -Y);
    const ull DSO2 = pk2(DSOF, DSOF);
    const ull M1   = pk2(-1.0f, -1.0f);
    const ull Bias = pk2(383.5f, 383.5f);
    const ull K19 = pk2(C19, C19), K17 = pk2(C17, C17), K15 = pk2(C15, C15);
    const ull K13 = pk2(C13, C13), K11 = pk2(C11, C11), K9  = pk2(C9,  C9);
    const ull K7  = pk2(C7,  C7),  K5  = pk2(C5,  C5),  K3  = pk2(C3,  C3);
    const ull K1  = pk2(C1,  C1);

    ull acc2 = 0ULL;   // packed (acc_batch0, acc_batch1)

    const float4* qp = d_qi + QBASE;     // local k=0 of view 0
    #pragma unroll 2
    for (int vp = 0; vp < NPAIR; vp++, qp += 2 * QSTRIDE) {
        float4 cs = strig[vp];
        ull cb2 = pk2(cs.x, cs.y);
        ull sb2 = pk2(cs.z, cs.w);

        // dt = DSO - (X*cb + Y*sb)  (>0);  cr = X*sb - Y*cb
        ull u2  = fma2(Y2, sb2, mul2(X2, cb2));
        ull dt2 = fma2(u2, M1, DSO2);
        ull cr2 = fma2(nY2, cb2, mul2(X2, sb2));

        float dtA, dtB, crA, crB;
        upk2(dt2, dtA, dtB);
        upk2(cr2, crA, crB);

        float ttA = __fdividef(crA, dtA);
        float ttB = __fdividef(crB, dtB);
        ull tt2 = pk2(ttA, ttB);
        ull t22 = mul2(tt2, tt2);

        ull p2 = fma2(K19, t22, K17);
        p2 = fma2(p2, t22, K15);
        p2 = fma2(p2, t22, K13);
        p2 = fma2(p2, t22, K11);
        p2 = fma2(p2, t22, K9);
        p2 = fma2(p2, t22, K7);
        p2 = fma2(p2, t22, K5);
        p2 = fma2(p2, t22, K3);
        p2 = fma2(p2, t22, K1);
        ull gidx2 = fma2(tt2, p2, Bias);      // atan(t)/DG + 383.5, per view

        float gA, gB;
        upk2(gidx2, gA, gB);

        // 1/L2 per view (L2 = dt^2 + cr^2)
        ull l22 = fma2(dt2, dt2, mul2(cr2, cr2));
        float l2A, l2B;
        upk2(l22, l2A, l2B);
        float rinA = __fdividef(1.0f, l2A);
        float rinB = __fdividef(1.0f, l2B);

        // ---- view A ----
        {
            float fi = floorf(gA);            // in [-13, 780]
            float wgt = gA - fi;
            int i0 = (int)fi;
            float4 qv = __ldg(&qp[i0]);       // (q0[k], q1[k], q0[k+1], q1[k+1])
            ull lo2 = pk2(qv.x, qv.y);
            ull hi2 = pk2(qv.z, qv.w);
            ull w2  = pk2(wgt, wgt);
            ull r2  = pk2(rinA, rinA);
            ull df2 = fma2(lo2, M1, hi2);     // hi - lo
            ull v2  = fma2(w2, df2, lo2);
            acc2 = fma2(v2, r2, acc2);
        }
        // ---- view B ----
        {
            float fi = floorf(gB);
            float wgt = gB - fi;
            int i0 = (int)fi;
            float4 qv = __ldg(&qp[QSTRIDE + i0]);
            ull lo2 = pk2(qv.x, qv.y);
            ull hi2 = pk2(qv.z, qv.w);
            ull w2  = pk2(wgt, wgt);
            ull r2  = pk2(rinB, rinB);
            ull df2 = fma2(lo2, M1, hi2);
            ull v2  = fma2(w2, df2, lo2);
            acc2 = fma2(v2, r2, acc2);
        }
    }

    float acc0, acc1;
    upk2(acc2, acc0, acc1);
    out[(size_t)y * IMG + x]                     = acc0 * SCALEF;
    out[(size_t)IMG * IMG + (size_t)y * IMG + x] = acc1 * SCALEF;
}

// ---------------- launch ----------------
extern "C" void kernel_launch(void* const* d_in, const int* in_sizes, int n_in,
                              void* d_out, int out_size) {
    (void)in_sizes; (void)n_in; (void)out_size;
    const float* proj = (const float*)d_in[0];
    float* out = (float*)d_out;

    filter_kernel<<<NVIEWS, 192>>>(proj);
    backproj_kernel<<<dim3(IMG / 32, IMG / 8), 256>>>(out);
}

// round 16
// speedup vs baseline: 1.8354x; 1.0479x over previous
#include <cuda_runtime.h>
#include <math.h>

// ---------------- fixed geometry ----------------
#define IMG    512
#define NDET   768
#define NVIEWS 360
#define NPAIR  (NVIEWS / 2)
#define QSTRIDE 800            // float4 row stride: 16 guard + 768 data + 16 guard
#define QBASE   16             // data starts at physical index 16

#define DG_D    (1.2858 / (595.0 + 490.6))        // DGAMMA (double)
#define DGF     ((float)DG_D)
#define INVDG_D ((595.0 + 490.6) / 1.2858)        // 1/DGAMMA
#define DSOF    595.0f
#define PIXF    0.7433f
#define SCALEF  ((float)(2.0 * M_PI / 360.0))
#define G0F     ((float)(1.0 / (8.0 * DG_D * DG_D)))

// asin series coefficients, pre-scaled by 1/DGAMMA (deg-13; |s| <= 0.4515,
// tail ~1e-4 detector bins)
#define A0 ((float)( INVDG_D))
#define A1 ((float)( INVDG_D * (1.0 / 6.0)))
#define A2 ((float)( INVDG_D * (3.0 / 40.0)))
#define A3 ((float)( INVDG_D * (15.0 / 336.0)))
#define A4 ((float)( INVDG_D * (35.0 / 1152.0)))
#define A5 ((float)( INVDG_D * (63.0 / 2816.0)))
#define A6 ((float)( INVDG_D * (231.0 / 13312.0)))

// ---------------- f32x2 packed helpers (sm_100+) ----------------
typedef unsigned long long ull;
__device__ __forceinline__ ull pk2(float lo, float hi) {
    ull r; asm("mov.b64 %0, {%1, %2};" : "=l"(r) : "f"(lo), "f"(hi)); return r;
}
__device__ __forceinline__ void upk2(ull v, float& lo, float& hi) {
    asm("mov.b64 {%0, %1}, %2;" : "=f"(lo), "=f"(hi) : "l"(v));
}
__device__ __forceinline__ ull fma2(ull a, ull b, ull c) {
    ull r; asm("fma.rn.f32x2 %0, %1, %2, %3;" : "=l"(r) : "l"(a), "l"(b), "l"(c)); return r;
}
__device__ __forceinline__ ull mul2(ull a, ull b) {
    ull r; asm("mul.rn.f32x2 %0, %1, %2;" : "=l"(r) : "l"(a), "l"(b)); return r;
}
__device__ __forceinline__ float rsqrt_approx(float x) {
    float r; asm("rsqrt.approx.f32 %0, %1;" : "=f"(r) : "f"(x)); return r;
}

// ---------------- device scratch ----------------
// Row v occupies d_qi[v*QSTRIDE .. +799]. Local index k in [-16, 783] maps to
// physical QBASE + k. Entry for k in [0,766]: (q0[k], q1[k], q0[k+1], q1[k+1]).
// All other entries (guards, k=767..783, k<0) are zeros.
__device__ float4 d_qi[NVIEWS * QSTRIDE];

// ramp kernel value g[i], i <-> n = i-767; zero for i > 1534
__device__ __forceinline__ float ramp_g(int i) {
    if (i > 2 * NDET - 2) return 0.0f;
    int n = i - (NDET - 1);
    if (n == 0) return G0F;
    if ((n & 1) == 0) return 0.0f;
    float s = (float)M_PI * sinf((float)n * DGF);
    return __fdividef(-0.5f, s * s);
}

// ---------------- 1) ramp filter (direct sparse convolution) ----------------
// One block (192 threads) per view. Thread t owns k = t, t+192, t+384, t+576.
// g4[i] = (g(i), g(i+192), g(i+384), g(i+576)); tap index i = k0 - j + 767 in [0,958].
__global__ void __launch_bounds__(192) filter_kernel(const float* __restrict__ proj) {
    __shared__ float4 g4[959];
    __shared__ float2 p01[NDET];          // cosine-weighted proj, both batches
    __shared__ float  qs0[NDET], qs1[NDET];

    const int v = blockIdx.x;
    const int t = threadIdx.x;

    for (int i = t; i < 959; i += 192)
        g4[i] = make_float4(ramp_g(i), ramp_g(i + 192), ramp_g(i + 384), ramp_g(i + 576));

    const float* p0 = proj + (size_t)v * NDET;
    const float* p1 = proj + (size_t)(NVIEWS + v) * NDET;
    for (int j = t; j < NDET; j += 192) {
        float cw = DSOF * cosf(((float)j - 383.5f) * DGF);
        p01[j] = make_float2(p0[j] * cw, p1[j] * cw);
    }
    __syncthreads();

    const int k0 = t;                     // outputs k0 + 192*m, m = 0..3 (same parity)
    float2 pc0 = p01[k0], pc1 = p01[k0 + 192], pc2 = p01[k0 + 384], pc3 = p01[k0 + 576];
    // packed accumulators: A* -> outputs (k0, k0+192), B* -> (k0+384, k0+576)
    ull Acc0 = pk2(pc0.x * G0F, pc1.x * G0F);     // batch 0
    ull Acc1 = pk2(pc0.y * G0F, pc1.y * G0F);     // batch 1
    ull Bcc0 = pk2(pc2.x * G0F, pc3.x * G0F);
    ull Bcc1 = pk2(pc2.y * G0F, pc3.y * G0F);

    const int j0 = (k0 & 1) ^ 1;          // opposite parity -> odd (k-j) only
    #pragma unroll 4
    for (int j = j0; j < NDET; j += 2) {
        float2 p = p01[j];
        float4 g = g4[k0 - j + (NDET - 1)];
        ull px2 = pk2(p.x, p.x);
        ull py2 = pk2(p.y, p.y);
        ull g01 = pk2(g.x, g.y);
        ull g23 = pk2(g.z, g.w);
        Acc0 = fma2(px2, g01, Acc0);
        Acc1 = fma2(py2, g01, Acc1);
        Bcc0 = fma2(px2, g23, Bcc0);
        Bcc1 = fma2(py2, g23, Bcc1);
    }

    float a0, a1, b0, b1;
    upk2(Acc0, a0, a1); qs0[k0] = a0 * DGF; qs0[k0 + 192] = a1 * DGF;
    upk2(Acc1, a0, a1); qs1[k0] = a0 * DGF; qs1[k0 + 192] = a1 * DGF;
    upk2(Bcc0, b0, b1); qs0[k0 + 384] = b0 * DGF; qs0[k0 + 576] = b1 * DGF;
    upk2(Bcc1, b0, b1); qs1[k0 + 384] = b0 * DGF; qs1[k0 + 576] = b1 * DGF;
    __syncthreads();

    // write row: entry k = (q0[k], q1[k], q0[k+1], q1[k+1]) for k in [0,766];
    // everything else (guards) zero.
    float4* row = d_qi + (size_t)v * QSTRIDE;        // physical base
    for (int i = t; i < QSTRIDE; i += 192) {
        int k = i - QBASE;
        row[i] = (k >= 0 && k < NDET - 1)
               ? make_float4(qs0[k], qs1[k], qs0[k + 1], qs1[k + 1])
               : make_float4(0.f, 0.f, 0.f, 0.f);
    }
}

// ---------------- 2) pixel-driven backprojection ----------------
// Block = 256 threads = one 32x8 pixel tile (grid 16x64 = 1024 CTAs).
// One pixel per thread; views in pairs with f32x2 packed arithmetic.
// gamma via asin(cr * rsqrt(L2)) — one MUFU.RSQ yields both the asin argument
// and rin = 1/L2 = rs^2. Deg-13 asin series in Estrin form (depth 4).
// No bounds checks: guard zeros absorb out-of-fan rays.
__global__ void __launch_bounds__(256) backproj_kernel(float* __restrict__ out) {
    __shared__ float4 strig[NPAIR];   // (cb_A, cb_B, sb_A, sb_B) per view pair

    const int t = threadIdx.x;
    if (t < NPAIR) {
        float sA, cA, sB, cB;
        sincosf((float)(2 * t)     * SCALEF, &sA, &cA);
        sincosf((float)(2 * t + 1) * SCALEF, &sB, &cB);
        strig[t] = make_float4(cA, cB, sA, sB);
    }
    __syncthreads();

    const int lane = t & 31, w = t >> 5;
    const int lx = lane & 7, ly = lane >> 3;
    const int wx = w & 3,   wy = w >> 2;
    const int x = blockIdx.x * 32 + wx * 8 + lx;
    const int y = blockIdx.y * 8  + wy * 4 + ly;

    const float X = ((float)x - 255.5f) * PIXF;
    const float Y = ((float)y - 255.5f) * PIXF;

    // hoisted packed constants
    const ull X2   = pk2(X, X);
    const ull Y2   = pk2(Y, Y);
    const ull nY2  = pk2(-Y, -Y);
    const ull DSO2 = pk2(DSOF, DSOF);
    const ull M1   = pk2(-1.0f, -1.0f);
    const ull Bias = pk2(383.5f, 383.5f);
    const ull KA0 = pk2(A0, A0), KA1 = pk2(A1, A1), KA2 = pk2(A2, A2);
    const ull KA3 = pk2(A3, A3), KA4 = pk2(A4, A4), KA5 = pk2(A5, A5);
    const ull KA6 = pk2(A6, A6);

    ull acc2 = 0ULL;   // packed (acc_batch0, acc_batch1)

    const float4* qp = d_qi + QBASE;     // local k=0 of view 0
    #pragma unroll 2
    for (int vp = 0; vp < NPAIR; vp++, qp += 2 * QSTRIDE) {
        float4 cs = strig[vp];
        ull cb2 = pk2(cs.x, cs.y);
        ull sb2 = pk2(cs.z, cs.w);

        // dt = DSO - (X*cb + Y*sb)  (>0);  cr = X*sb - Y*cb
        ull u2  = fma2(Y2, sb2, mul2(X2, cb2));
        ull dt2 = fma2(u2, M1, DSO2);
        ull cr2 = fma2(nY2, cb2, mul2(X2, sb2));
        ull l22 = fma2(dt2, dt2, mul2(cr2, cr2));     // L2 = dt^2+cr^2

        float l2A, l2B;
        upk2(l22, l2A, l2B);
        float rsA = rsqrt_approx(l2A);
        float rsB = rsqrt_approx(l2B);
        float rinA = rsA * rsA;                        // 1/L2
        float rinB = rsB * rsB;

        ull s2 = mul2(cr2, pk2(rsA, rsB));             // sin(gamma), |s|<=0.4515
        ull u  = mul2(s2, s2);                         // s^2

        // Estrin deg-13: P = (a0+a1 u) + u^2 (a2+a3 u) + u^4 ((a4+a5 u) + u^2 a6)
        ull q0 = fma2(KA1, u, KA0);
        ull q1 = fma2(KA3, u, KA2);
        ull q2 = fma2(KA5, u, KA4);
        ull um2 = mul2(u, u);
        ull r0 = fma2(q1, um2, q0);
        ull r1 = fma2(KA6, um2, q2);
        ull um4 = mul2(um2, um2);
        ull P  = fma2(r1, um4, r0);
        ull gidx2 = fma2(s2, P, Bias);                 // asin(s)/DG + 383.5

        float gA, gB;
        upk2(gidx2, gA, gB);

        // ---- view A ----
        {
            int i0 = __float2int_rd(gA);               // in [-13, 780]
            float wgt = gA - __int2float_rn(i0);
            float4 qv = __ldg(&qp[i0]);                // (q0[k], q1[k], q0[k+1], q1[k+1])
            ull lo2 = pk2(qv.x, qv.y);
            ull hi2 = pk2(qv.z, qv.w);
            ull w2  = pk2(wgt, wgt);
            ull r2  = pk2(rinA, rinA);
            ull df2 = fma2(lo2, M1, hi2);              // hi - lo
            ull v2  = fma2(w2, df2, lo2);
            acc2 = fma2(v2, r2, acc2);
        }
        // ---- view B ----
        {
            int i0 = __float2int_rd(gB);
            float wgt = gB - __int2float_rn(i0);
            float4 qv = __ldg(&qp[QSTRIDE + i0]);
            ull lo2 = pk2(qv.x, qv.y);
            ull hi2 = pk2(qv.z, qv.w);
            ull w2  = pk2(wgt, wgt);
            ull r2  = pk2(rinB, rinB);
            ull df2 = fma2(lo2, M1, hi2);
            ull v2  = fma2(w2, df2, lo2);
            acc2 = fma2(v2, r2, acc2);
        }
    }

    float acc0, acc1;
    upk2(acc2, acc0, acc1);
    out[(size_t)y * IMG + x]                     = acc0 * SCALEF;
    out[(size_t)IMG * IMG + (size_t)y * IMG + x] = acc1 * SCALEF;
}

// ---------------- launch ----------------
extern "C" void kernel_launch(void* const* d_in, const int* in_sizes, int n_in,
                              void* d_out, int out_size) {
    (void)in_sizes; (void)n_in; (void)out_size;
    const float* proj = (const float*)d_in[0];
    float* out = (float*)d_out;

    filter_kernel<<<NVIEWS, 192>>>(proj);
    backproj_kernel<<<dim3(IMG / 32, IMG / 8), 256>>>(out);
}